// round 13
// baseline (speedup 1.0000x reference)
#include <cuda_runtime.h>
#include <cuda_fp16.h>
#include <mma.h>
using namespace nvcuda;

#define N 2048
#define D 128
#define R 43
#define KSPLIT 16
#define JSPAN (N / KSPLIT)   // 128
#define ITILE 64
#define CHUNK 16
#define NCHUNK (JSPAN / CHUNK)  // 8

// -------- scratch (device globals: no allocation allowed) --------
__device__ __half g_ehi[(size_t)N * N];    // E hi plane (8.4 MB)
__device__ __half g_elo[(size_t)N * N];    // E lo plane (8.4 MB)
__device__ __half g_xhi[N * D];            // XS*256 hi plane
__device__ __half g_xlo[N * D];            // XS*256 lo plane
__device__ float g_head[N];
__device__ float g_tail[N];
__device__ float g_colsum[N];              // softmax denominators (atomic)

// ---- cp.async helpers ----
__device__ __forceinline__ void cpasync16(void* dst, const void* src) {
    unsigned d = (unsigned)__cvta_generic_to_shared(dst);
    asm volatile("cp.async.cg.shared.global [%0], [%1], 16;" :: "r"(d), "l"(src));
}
#define CP_COMMIT() asm volatile("cp.async.commit_group;")
#define CP_WAIT1()  asm volatile("cp.async.wait_group 1;")

// ================= K1: head/tail projections + zero colsum + zero d_out ==========
__global__ void k_headtail(const float* __restrict__ inp,
                           const float* __restrict__ wh, const float* __restrict__ bh,
                           const float* __restrict__ wt, const float* __restrict__ bt,
                           float* __restrict__ out) {
    int gt = blockIdx.x * blockDim.x + threadIdx.x;     // 65536 threads
    ((float4*)out)[gt] = make_float4(0.f, 0.f, 0.f, 0.f);
    if (gt < N) g_colsum[gt] = 0.f;
    int warp = gt >> 5;
    int lane = threadIdx.x & 31;
    float4 x = ((const float4*)inp)[warp * 32 + lane];
    float4 a = ((const float4*)wh)[lane];
    float4 b = ((const float4*)wt)[lane];
    float h = x.x * a.x + x.y * a.y + x.z * a.z + x.w * a.w;
    float t = x.x * b.x + x.y * b.y + x.z * b.z + x.w * b.w;
#pragma unroll
    for (int o = 16; o; o >>= 1) {
        h += __shfl_xor_sync(0xffffffffu, h, o);
        t += __shfl_xor_sync(0xffffffffu, t, o);
    }
    if (lane == 0) {
        g_head[warp] = h + bh[0];
        g_tail[warp] = t + bt[0];
    }
}

// ================= K2: E = exp(logits) in fp16 hi/lo planes + fused column sums ===
// One block = 256 consecutive (i,j) pairs. 44 KB of relation staged via __ldcs
// float4, fully unrolled (front-batched LDG -> MLP hides DRAM latency). Dot reads
// smem at stride 43 (coprime 32) -> conflict-free. Column sums via fire-and-forget
// atomicAdd (spread addresses). hi+lo summed -> normalization consistent with the
// quantized E. max|logit| ~ 7.6 -> e <= ~2000: fp16-safe, no-max-pass fp32-safe.
__global__ void __launch_bounds__(256) k_logexp(const float* __restrict__ rel,
                                                const float* __restrict__ mask,
                                                const float* __restrict__ wrel,
                                                const float* __restrict__ brel) {
    __shared__ float sw[48];
    __shared__ __align__(16) float sd[256 * R];
    int tid = threadIdx.x;
    if (tid < R) sw[tid] = wrel[tid];

    size_t p0 = (size_t)blockIdx.x * 256;
    const float4* src = (const float4*)(rel + p0 * R);
#pragma unroll
    for (int u = 0; u < 11; u++) {
        int k = tid + u * 256;
        if (k < (256 * R) / 4)
            ((float4*)sd)[k] = __ldcs(src + k);
    }
    __syncthreads();

    size_t p = p0 + tid;
    int i = (int)(p >> 11);
    int j = (int)(p & (N - 1));

    float acc = brel[0];
#pragma unroll
    for (int r = 0; r < R; r++)
        acc = fmaf(sd[tid * R + r], sw[r], acc);

    float logit = acc + __ldg(g_head + i) + __ldg(g_tail + j) + __ldcs(mask + p);
    float e = __expf(logit);
    __half hi = __float2half_rn(e);
    float hif = __half2float(hi);
    __half lo = __float2half_rn(e - hif);
    g_ehi[p] = hi;
    g_elo[p] = lo;
    atomicAdd(&g_colsum[j], hif + __half2float(lo));
}

// ================= K3: XS = inp * (256/colsum), fp16 hi/lo planes =================
// x256 keeps xs out of fp16 denormal range; epilogue multiplies by 2^-8.
__global__ void k_xsplit(const float* __restrict__ inp) {
    int t = blockIdx.x * 256 + threadIdx.x;       // 65536 threads, 4 elems each
    int j = t >> 5;
    float rc = __fdividef(256.f, g_colsum[j]);
    float4 v = ((const float4*)inp)[t];
    float f0 = v.x * rc, f1 = v.y * rc, f2 = v.z * rc, f3 = v.w * rc;
    __half h0 = __float2half_rn(f0), h1 = __float2half_rn(f1);
    __half h2 = __float2half_rn(f2), h3 = __float2half_rn(f3);
    __half l0 = __float2half_rn(f0 - __half2float(h0));
    __half l1 = __float2half_rn(f1 - __half2float(h1));
    __half l2 = __float2half_rn(f2 - __half2float(h2));
    __half l3 = __float2half_rn(f3 - __half2float(h3));
    ((__half2*)g_xhi)[2 * t]     = __halves2half2(h0, h1);
    ((__half2*)g_xhi)[2 * t + 1] = __halves2half2(h2, h3);
    ((__half2*)g_xlo)[2 * t]     = __halves2half2(l0, l1);
    ((__half2*)g_xlo)[2 * t + 1] = __halves2half2(l2, l3);
}

// ================= K4: split-K tensor GEMM, cp.async 3-stage, atomic epilogue =====
// (launch index 3 -> profiled)
// Grid (32, 16): 32 i-tiles of 64 rows x 16 K-splits of 128 j; chunks of 16 j.
// 8 warps in 4i x 2d: warp tile 16i x 64d (acc[4]). fp16 hi/lo planes pre-split in
// gmem -> staging is pure LDGSTS (no unpack ALU, no staging regs). 3-stage pipeline,
// one __syncthreads per chunk. Products: hi*hi + hi*lo + lo*hi (lo*lo ~2^-24).
__global__ void __launch_bounds__(256) k_gemm(float* __restrict__ out) {
    __shared__ __align__(16) __half sE[2][3][ITILE][24];   // 18.4 KB (rows 48B)
    __shared__ __align__(16) __half sX[2][3][CHUNK][136];  // 26.1 KB (rows 272B)
    int tid = threadIdx.x;
    int lane = tid & 31;
    int w = tid >> 5;
    int i0 = blockIdx.x * ITILE;
    int jbeg = blockIdx.y * JSPAN;
    int wi = w >> 1;                 // 0..3 -> i offset 16*wi
    int wd = w & 1;                  // 0..1 -> d offset 64*wd

    // staging task coords (fixed per thread)
    int er = tid >> 2;                       // 0..63
    int eseg = tid & 1;                      // 0..1 (16B segment)
    int epl = (tid >> 1) & 1;                // plane
    const __half* esrc = (epl ? g_elo : g_ehi) + (size_t)(i0 + er) * N + jbeg + eseg * 8;

    wmma::fragment<wmma::accumulator, 16, 16, 16, float> acc[4];
#pragma unroll
    for (int dt = 0; dt < 4; dt++) wmma::fill_fragment(acc[dt], 0.f);

#define ISSUE(c) do {                                                          \
        int _st = (c) % 3, _jg = (c) * CHUNK;                                  \
        cpasync16(&sE[epl][_st][er][eseg * 8], esrc + _jg);                    \
        _Pragma("unroll")                                                      \
        for (int _m = 0; _m < 2; _m++) {                                       \
            int _k = tid + 256 * _m;                                           \
            int _xr = _k >> 5, _rem = _k & 31;                                 \
            int _xpl = _rem >> 4, _xseg = _rem & 15;                           \
            const __half* _xs = (_xpl ? g_xlo : g_xhi)                         \
                + (jbeg + _jg + _xr) * D + _xseg * 8;                          \
            cpasync16(&sX[_xpl][_st][_xr][_xseg * 8], _xs);                    \
        }                                                                      \
    } while (0)

    ISSUE(0); CP_COMMIT();
    ISSUE(1); CP_COMMIT();

    for (int c = 0; c < NCHUNK; c++) {
        CP_WAIT1();
        __syncthreads();
        if (c + 2 < NCHUNK) ISSUE(c + 2);
        CP_COMMIT();

        int st = c % 3;
        wmma::fragment<wmma::matrix_a, 16, 16, 16, __half, wmma::row_major> ahi, alo;
        wmma::load_matrix_sync(ahi, &sE[0][st][wi * 16][0], 24);
        wmma::load_matrix_sync(alo, &sE[1][st][wi * 16][0], 24);
#pragma unroll
        for (int dt = 0; dt < 4; dt++) {
            wmma::fragment<wmma::matrix_b, 16, 16, 16, __half, wmma::row_major> bhi, blo;
            wmma::load_matrix_sync(bhi, &sX[0][st][0][wd * 64 + dt * 16], 136);
            wmma::load_matrix_sync(blo, &sX[1][st][0][wd * 64 + dt * 16], 136);
            wmma::mma_sync(acc[dt], ahi, bhi, acc[dt]);
            wmma::mma_sync(acc[dt], ahi, blo, acc[dt]);
            wmma::mma_sync(acc[dt], alo, bhi, acc[dt]);
        }
    }
#undef ISSUE

    // epilogue: fragments -> per-warp smem (aliases sE) -> atomicAdd, undo x256
    __syncthreads();
    float* sOut = ((float*)&sE[0][0][0][0]) + w * 256;
    float* dstw = out + (size_t)(i0 + wi * 16) * D + wd * 64;
#pragma unroll
    for (int dt = 0; dt < 4; dt++) {
        wmma::store_matrix_sync(sOut, acc[dt], 16, wmma::mem_row_major);
        __syncwarp();
#pragma unroll
        for (int q = lane; q < 256; q += 32) {
            int rr = q >> 4, cc = q & 15;
            atomicAdd(dstw + (size_t)rr * D + dt * 16 + cc, sOut[q] * 0.00390625f);
        }
        __syncwarp();
    }
}

// ================= launch =================
extern "C" void kernel_launch(void* const* d_in, const int* in_sizes, int n_in,
                              void* d_out, int out_size) {
    const float* inputs   = (const float*)d_in[0];
    const float* relation = (const float*)d_in[1];
    const float* rel_mask = (const float*)d_in[2];
    const float* w_rel    = (const float*)d_in[3];
    const float* b_rel    = (const float*)d_in[4];
    const float* w_head   = (const float*)d_in[5];
    const float* b_head   = (const float*)d_in[6];
    const float* w_tail   = (const float*)d_in[7];
    const float* b_tail   = (const float*)d_in[8];
    float* out = (float*)d_out;

    k_headtail<<<256, 256>>>(inputs, w_head, b_head, w_tail, b_tail, out);  // idx 0
    k_logexp<<<(N * N) / 256, 256>>>(relation, rel_mask, w_rel, b_rel);     // idx 1
    k_xsplit<<<256, 256>>>(inputs);                                         // idx 2
    k_gemm<<<dim3(N / ITILE, KSPLIT), 256>>>(out);                          // idx 3 (profiled)
}

// round 14
// speedup vs baseline: 1.2368x; 1.2368x over previous
#include <cuda_runtime.h>
#include <cuda_bf16.h>
#include <mma.h>
using namespace nvcuda;

#define N 2048
#define D 128
#define R 43
#define KSPLIT 16
#define JSPAN (N / KSPLIT)   // 128
#define ITILE 64

// -------- scratch (device globals: no allocation allowed) --------
__device__ unsigned g_e2[(size_t)N * N];   // packed E: (bf16 hi) | (bf16 lo << 16)
__device__ unsigned g_x2[N * D];           // packed XS = inp*recip, hi/lo bf16 (1 MB)
__device__ float g_head[N];
__device__ float g_tail[N];
__device__ float g_colsum[N];              // softmax denominators (atomic)

__global__ void k_nop() {}

// ================= K1: head/tail projections + zero colsum + zero d_out ==========
__global__ void k_headtail(const float* __restrict__ inp,
                           const float* __restrict__ wh, const float* __restrict__ bh,
                           const float* __restrict__ wt, const float* __restrict__ bt,
                           float* __restrict__ out) {
    int gt = blockIdx.x * blockDim.x + threadIdx.x;     // 65536 threads
    ((float4*)out)[gt] = make_float4(0.f, 0.f, 0.f, 0.f);  // zero 1 MB output
    if (gt < N) g_colsum[gt] = 0.f;
    int warp = gt >> 5;
    int lane = threadIdx.x & 31;
    float4 x = ((const float4*)inp)[warp * 32 + lane];
    float4 a = ((const float4*)wh)[lane];
    float4 b = ((const float4*)wt)[lane];
    float h = x.x * a.x + x.y * a.y + x.z * a.z + x.w * a.w;
    float t = x.x * b.x + x.y * b.y + x.z * b.z + x.w * b.w;
#pragma unroll
    for (int o = 16; o; o >>= 1) {
        h += __shfl_xor_sync(0xffffffffu, h, o);
        t += __shfl_xor_sync(0xffffffffu, t, o);
    }
    if (lane == 0) {
        g_head[warp] = h + bh[0];
        g_tail[warp] = t + bt[0];
    }
}

// ================= K2: E = exp(logits), packed bf16 hi/lo + fused column sums =====
// (launch index 3 this round -> PROFILED)
// One block = 256 consecutive (i,j) pairs. 44 KB of relation staged via __ldcs
// float4, fully unrolled (11 front-batched LDG.128 -> MLP hides DRAM latency).
// Dot reads smem at stride 43 (coprime 32) -> conflict-free. Column sums via one
// fire-and-forget atomicAdd per thread (spread addresses). Summing hi+lo keeps
// normalization exactly consistent with the quantized E. max|logit| ~ 8 -> exp
// without the max pass is safe in fp32 (softmax shift-invariant). E written as ONE
// packed STG.32 stream — R13 showed two 16-bit plane stores cost ~45 us here.
__global__ void __launch_bounds__(256) k_logexp(const float* __restrict__ rel,
                                                const float* __restrict__ mask,
                                                const float* __restrict__ wrel,
                                                const float* __restrict__ brel) {
    __shared__ float sw[48];
    __shared__ __align__(16) float sd[256 * R];
    int tid = threadIdx.x;
    if (tid < R) sw[tid] = wrel[tid];

    size_t p0 = (size_t)blockIdx.x * 256;
    const float4* src = (const float4*)(rel + p0 * R);
#pragma unroll
    for (int u = 0; u < 11; u++) {
        int k = tid + u * 256;
        if (k < (256 * R) / 4)
            ((float4*)sd)[k] = __ldcs(src + k);
    }
    __syncthreads();

    size_t p = p0 + tid;
    int i = (int)(p >> 11);
    int j = (int)(p & (N - 1));

    float acc = brel[0];
#pragma unroll
    for (int r = 0; r < R; r++)
        acc = fmaf(sd[tid * R + r], sw[r], acc);

    float logit = acc + __ldg(g_head + i) + __ldg(g_tail + j) + __ldcs(mask + p);
    float e = __expf(logit);
    __nv_bfloat16 hi = __float2bfloat16(e);
    float hif = __bfloat162float(hi);
    __nv_bfloat16 lo = __float2bfloat16(e - hif);
    g_e2[p] = (unsigned)__bfloat16_as_ushort(hi)
            | ((unsigned)__bfloat16_as_ushort(lo) << 16);
    atomicAdd(&g_colsum[j], hif + __bfloat162float(lo));
}

// ================= K3: XS = inp * (1/colsum), packed bf16 hi/lo ==================
__global__ void k_xsplit(const float* __restrict__ inp) {
    int t = blockIdx.x * 256 + threadIdx.x;       // 65536 threads, 4 elems each
    int j = t >> 5;                                // 32 float4 per row
    float rc = __fdividef(1.f, g_colsum[j]);
    float4 v = ((const float4*)inp)[t];
    v.x *= rc; v.y *= rc; v.z *= rc; v.w *= rc;
    uint4 o;
    float f, hf;
#define SPLIT(dst, val) \
    f = (val); hf = __bfloat162float(__float2bfloat16(f)); \
    dst = (unsigned)__bfloat16_as_ushort(__float2bfloat16(f)) \
        | ((unsigned)__bfloat16_as_ushort(__float2bfloat16(f - hf)) << 16)
    SPLIT(o.x, v.x); SPLIT(o.y, v.y); SPLIT(o.z, v.z); SPLIT(o.w, v.w);
#undef SPLIT
    ((uint4*)g_x2)[t] = o;
}

// ================= K4: split-K tensor-core GEMM, atomic accumulate to out ========
// Grid (32, 16): 32 i-tiles of 64 rows x 16 K-splits of 128 j. 8 warps in 4i x 2d:
// warp tile 16i x 64d (acc[4]). Hi/lo bf16 decomposition of BOTH operands
// (pre-packed in gmem): hi*hi + hi*lo + lo*hi per tile (lo*lo ~2^-18 dropped).
// Register double-buffering: next chunk's 6 uint4 LDGs issued before the mma loop
// consumes current smem -> gmem latency overlaps tensor work.
__global__ void __launch_bounds__(256, 2) k_gemm(float* __restrict__ out) {
    __shared__ __align__(16) __nv_bfloat16 sEhi[ITILE][40];
    __shared__ __align__(16) __nv_bfloat16 sElo[ITILE][40];
    __shared__ __align__(16) __nv_bfloat16 sXhi[32][136];
    __shared__ __align__(16) __nv_bfloat16 sXlo[32][136];
    __shared__ float sOut[8][256];
    int tid = threadIdx.x;
    int i0 = blockIdx.x * ITILE;
    int jbeg = blockIdx.y * JSPAN;
    int lane = tid & 31;
    int w = tid >> 5;
    int wi = w >> 1;                 // 0..3 -> i offset 16*wi
    int wd = w & 1;                  // 0..1 -> d offset 64*wd

    // staging coords (constant per thread)
    int er0 = tid >> 3, ec0 = (tid & 7) * 4;            // E part 0: k = tid
    int er1 = (tid + 256) >> 3, ec1 = ec0;              // E part 1: k = tid+256
    const uint4* pe0 = (const uint4*)(g_e2 + (size_t)(i0 + er0) * N + jbeg + ec0);
    const uint4* pe1 = (const uint4*)(g_e2 + (size_t)(i0 + er1) * N + jbeg + ec1);

    wmma::fragment<wmma::accumulator, 16, 16, 16, float> acc[4];
#pragma unroll
    for (int dt = 0; dt < 4; dt++) wmma::fill_fragment(acc[dt], 0.f);

    uint4 ue0, ue1, ux[4];
    // prologue: load chunk jc=0
    ue0 = pe0[0];
    ue1 = pe1[0];
#pragma unroll
    for (int m = 0; m < 4; m++) {
        int k = tid + 256 * m;
        int jr = k >> 5, c4 = (k & 31) * 4;
        ux[m] = *(const uint4*)(g_x2 + (jbeg + jr) * D + c4);
    }

    for (int jc = 0; jc < JSPAN; jc += 32) {
        // unpack current regs -> smem
        {
            *(uint2*)&sEhi[er0][ec0] = make_uint2(
                (ue0.x & 0xffffu) | (ue0.y << 16), (ue0.z & 0xffffu) | (ue0.w << 16));
            *(uint2*)&sElo[er0][ec0] = make_uint2(
                (ue0.x >> 16) | (ue0.y & 0xffff0000u), (ue0.z >> 16) | (ue0.w & 0xffff0000u));
            *(uint2*)&sEhi[er1][ec1] = make_uint2(
                (ue1.x & 0xffffu) | (ue1.y << 16), (ue1.z & 0xffffu) | (ue1.w << 16));
            *(uint2*)&sElo[er1][ec1] = make_uint2(
                (ue1.x >> 16) | (ue1.y & 0xffff0000u), (ue1.z >> 16) | (ue1.w & 0xffff0000u));
#pragma unroll
            for (int m = 0; m < 4; m++) {
                int k = tid + 256 * m;
                int jr = k >> 5, c4 = (k & 31) * 4;
                *(uint2*)&sXhi[jr][c4] = make_uint2(
                    (ux[m].x & 0xffffu) | (ux[m].y << 16),
                    (ux[m].z & 0xffffu) | (ux[m].w << 16));
                *(uint2*)&sXlo[jr][c4] = make_uint2(
                    (ux[m].x >> 16) | (ux[m].y & 0xffff0000u),
                    (ux[m].z >> 16) | (ux[m].w & 0xffff0000u));
            }
        }
        __syncthreads();

        // prefetch next chunk while mma consumes smem
        int jn = jc + 32;
        if (jn < JSPAN) {
            ue0 = pe0[jn / 4];
            ue1 = pe1[jn / 4];
#pragma unroll
            for (int m = 0; m < 4; m++) {
                int k = tid + 256 * m;
                int jr = k >> 5, c4 = (k & 31) * 4;
                ux[m] = *(const uint4*)(g_x2 + (jbeg + jn + jr) * D + c4);
            }
        }

#pragma unroll
        for (int jj = 0; jj < 32; jj += 16) {
            wmma::fragment<wmma::matrix_a, 16, 16, 16, __nv_bfloat16, wmma::row_major> ahi, alo;
            wmma::load_matrix_sync(ahi, &sEhi[wi * 16][jj], 40);
            wmma::load_matrix_sync(alo, &sElo[wi * 16][jj], 40);
#pragma unroll
            for (int dt = 0; dt < 4; dt++) {
                wmma::fragment<wmma::matrix_b, 16, 16, 16, __nv_bfloat16, wmma::row_major> bhi, blo;
                wmma::load_matrix_sync(bhi, &sXhi[jj][wd * 64 + dt * 16], 136);
                wmma::load_matrix_sync(blo, &sXlo[jj][wd * 64 + dt * 16], 136);
                wmma::mma_sync(acc[dt], ahi, bhi, acc[dt]);
                wmma::mma_sync(acc[dt], ahi, blo, acc[dt]);
                wmma::mma_sync(acc[dt], alo, bhi, acc[dt]);
            }
        }
        __syncthreads();
    }

    // epilogue: fragments -> per-warp smem -> atomicAdd into out
    float* dstw = out + (size_t)(i0 + wi * 16) * D + wd * 64;
#pragma unroll
    for (int dt = 0; dt < 4; dt++) {
        wmma::store_matrix_sync(&sOut[w][0], acc[dt], 16, wmma::mem_row_major);
        __syncwarp();
#pragma unroll
        for (int q = lane; q < 256; q += 32) {
            int rr = q >> 4, cc = q & 15;
            atomicAdd(dstw + (size_t)rr * D + dt * 16 + cc, sOut[w][q]);
        }
        __syncwarp();
    }
}

// ================= launch =================
extern "C" void kernel_launch(void* const* d_in, const int* in_sizes, int n_in,
                              void* d_out, int out_size) {
    const float* inputs   = (const float*)d_in[0];
    const float* relation = (const float*)d_in[1];
    const float* rel_mask = (const float*)d_in[2];
    const float* w_rel    = (const float*)d_in[3];
    const float* b_rel    = (const float*)d_in[4];
    const float* w_head   = (const float*)d_in[5];
    const float* b_head   = (const float*)d_in[6];
    const float* w_tail   = (const float*)d_in[7];
    const float* b_tail   = (const float*)d_in[8];
    float* out = (float*)d_out;

    // 2 no-ops place k_logexp (the 63%-of-runtime kernel) at the profiled launch idx 3
    k_nop<<<1, 32>>>();                                                     // idx 0
    k_nop<<<1, 32>>>();                                                     // idx 1
    k_headtail<<<256, 256>>>(inputs, w_head, b_head, w_tail, b_tail, out);  // idx 2
    k_logexp<<<(N * N) / 256, 256>>>(relation, rel_mask, w_rel, b_rel);     // idx 3 (profiled)
    k_xsplit<<<256, 256>>>(inputs);                                         // idx 4
    k_gemm<<<dim3(N / ITILE, KSPLIT), 256>>>(out);                          // idx 5
}

// round 15
// speedup vs baseline: 1.2846x; 1.0386x over previous
#include <cuda_runtime.h>
#include <cuda_bf16.h>
#include <mma.h>
using namespace nvcuda;

#define N 2048
#define D 128
#define R 43
#define KSPLIT 16
#define JSPAN (N / KSPLIT)   // 128
#define ITILE 64
#define TP 128               // pairs per logexp tile
#define NT 4                 // tiles per logexp block
#define TFLOAT4 ((TP * R) / 4)  // 1376 float4 per tile

// -------- scratch (device globals: no allocation allowed) --------
__device__ unsigned g_e2[(size_t)N * N];   // packed E: (bf16 hi) | (bf16 lo << 16)
__device__ unsigned g_x2[N * D];           // packed XS = inp*recip, hi/lo bf16 (1 MB)
__device__ float g_head[N];
__device__ float g_tail[N];
__device__ float g_colsum[N];              // softmax denominators (atomic)

__device__ __forceinline__ void cpasync16(void* dst, const void* src) {
    unsigned d = (unsigned)__cvta_generic_to_shared(dst);
    asm volatile("cp.async.cg.shared.global [%0], [%1], 16;" :: "r"(d), "l"(src));
}

// ================= K1: head/tail projections + zero colsum + zero d_out ==========
__global__ void k_headtail(const float* __restrict__ inp,
                           const float* __restrict__ wh, const float* __restrict__ bh,
                           const float* __restrict__ wt, const float* __restrict__ bt,
                           float* __restrict__ out) {
    int gt = blockIdx.x * blockDim.x + threadIdx.x;     // 65536 threads
    ((float4*)out)[gt] = make_float4(0.f, 0.f, 0.f, 0.f);
    if (gt < N) g_colsum[gt] = 0.f;
    int warp = gt >> 5;
    int lane = threadIdx.x & 31;
    float4 x = ((const float4*)inp)[warp * 32 + lane];
    float4 a = ((const float4*)wh)[lane];
    float4 b = ((const float4*)wt)[lane];
    float h = x.x * a.x + x.y * a.y + x.z * a.z + x.w * a.w;
    float t = x.x * b.x + x.y * b.y + x.z * b.z + x.w * b.w;
#pragma unroll
    for (int o = 16; o; o >>= 1) {
        h += __shfl_xor_sync(0xffffffffu, h, o);
        t += __shfl_xor_sync(0xffffffffu, t, o);
    }
    if (lane == 0) {
        g_head[warp] = h + bh[0];
        g_tail[warp] = t + bt[0];
    }
}

// ================= K2: E = exp(logits), cp.async double-buffered pipeline =========
// R14 profile: DRAM 69.7% — loads idle during each block's compute phase. Now each
// block walks NT=4 consecutive 128-pair tiles with 2 smem buffers: tile t+1's
// LDGSTS stream is in flight while tile t computes -> DRAM stays busy.
// Warps 0-3 compute r[0,22) partials, warps 4-7 r[22,43) (no intra-warp divergence);
// halves combine via a 512B smem exchange on the barrier that also frees the buffer.
// LDS banks: (11q + r) mod 32 distinct across a warp -> conflict-free.
// E written as ONE packed STG.32 stream (R13: split 16-bit planes cost ~45 us).
// max|logit| ~ 8 -> exp without the max pass is safe in fp32 (shift-invariant).
__global__ void __launch_bounds__(256) k_logexp(const float* __restrict__ rel,
                                                const float* __restrict__ mask,
                                                const float* __restrict__ wrel,
                                                const float* __restrict__ brel) {
    __shared__ float sw[44];
    __shared__ __align__(16) float sd[2][TP * R];   // 2 x 22 KB
    __shared__ float sred[TP];
    int tid = threadIdx.x;
    if (tid < R) sw[tid] = wrel[tid];

    size_t t0 = (size_t)blockIdx.x * NT;            // first tile of this block
    const float4* base4 = (const float4*)rel;       // tile tt starts at tt*TFLOAT4

#define ISSUE(tt, buf) do {                                                    \
        const float4* _s = base4 + (size_t)(tt) * TFLOAT4;                     \
        _Pragma("unroll")                                                      \
        for (int _u = 0; _u < 6; _u++) {                                       \
            int _k = tid + _u * 256;                                           \
            if (_k < TFLOAT4)                                                  \
                cpasync16(&sd[buf][_k * 4], _s + _k);                          \
        }                                                                      \
    } while (0)

    ISSUE(t0, 0);
    asm volatile("cp.async.commit_group;");
    ISSUE(t0 + 1, 1);
    asm volatile("cp.async.commit_group;");

    int q = tid & (TP - 1);          // pair within tile
    int h = tid >> 7;                // 0: r[0,22)  1: r[22,43)

    for (int t = 0; t < NT; t++) {
        int buf = t & 1;
        asm volatile("cp.async.wait_group 1;");
        __syncthreads();                              // buf data visible

        const float* row = &sd[buf][q * R];
        float dot = 0.f;
        if (h) {
#pragma unroll
            for (int r = 22; r < R; r++) dot = fmaf(row[r], sw[r], dot);
            sred[q] = dot;
        } else {
#pragma unroll
            for (int r = 0; r < 22; r++) dot = fmaf(row[r], sw[r], dot);
        }
        __syncthreads();                              // sred ready + buf free

        if (t + 2 < NT) ISSUE(t0 + t + 2, buf);
        asm volatile("cp.async.commit_group;");

        if (!h) {
            size_t p = (t0 + t) * (size_t)TP + q;
            int i = (int)(p >> 11);
            int j = (int)(p & (N - 1));
            float logit = dot + sred[q] + brel[0]
                        + __ldg(g_head + i) + __ldg(g_tail + j) + __ldcs(mask + p);
            float e = __expf(logit);
            __nv_bfloat16 hi = __float2bfloat16(e);
            float hif = __bfloat162float(hi);
            __nv_bfloat16 lo = __float2bfloat16(e - hif);
            unsigned pk = (unsigned)__bfloat16_as_ushort(hi)
                        | ((unsigned)__bfloat16_as_ushort(lo) << 16);
            __stcs(g_e2 + p, pk);
            atomicAdd(&g_colsum[j], hif + __bfloat162float(lo));
        }
    }
#undef ISSUE
}

// ================= K3: XS = inp * (1/colsum), packed bf16 hi/lo ==================
__global__ void k_xsplit(const float* __restrict__ inp) {
    int t = blockIdx.x * 256 + threadIdx.x;       // 65536 threads, 4 elems each
    int j = t >> 5;
    float rc = __fdividef(1.f, g_colsum[j]);
    float4 v = ((const float4*)inp)[t];
    v.x *= rc; v.y *= rc; v.z *= rc; v.w *= rc;
    uint4 o;
    float f, hf;
#define SPLIT(dst, val) \
    f = (val); hf = __bfloat162float(__float2bfloat16(f)); \
    dst = (unsigned)__bfloat16_as_ushort(__float2bfloat16(f)) \
        | ((unsigned)__bfloat16_as_ushort(__float2bfloat16(f - hf)) << 16)
    SPLIT(o.x, v.x); SPLIT(o.y, v.y); SPLIT(o.z, v.z); SPLIT(o.w, v.w);
#undef SPLIT
    ((uint4*)g_x2)[t] = o;
}

// ================= K4: split-K tensor-core GEMM, atomic accumulate to out ========
// (launch index 3 -> profiled)
// Grid (32, 16): 32 i-tiles of 64 rows x 16 K-splits of 128 j. 8 warps in 4i x 2d:
// warp tile 16i x 64d (acc[4]). Hi/lo bf16 decomposition of BOTH operands
// (pre-packed): hi*hi + hi*lo + lo*hi per tile (lo*lo ~2^-18 dropped). Register
// double-buffering: next chunk's 6 uint4 LDGs issued before the mma loop.
__global__ void __launch_bounds__(256, 2) k_gemm(float* __restrict__ out) {
    __shared__ __align__(16) __nv_bfloat16 sEhi[ITILE][40];
    __shared__ __align__(16) __nv_bfloat16 sElo[ITILE][40];
    __shared__ __align__(16) __nv_bfloat16 sXhi[32][136];
    __shared__ __align__(16) __nv_bfloat16 sXlo[32][136];
    __shared__ float sOut[8][256];
    int tid = threadIdx.x;
    int i0 = blockIdx.x * ITILE;
    int jbeg = blockIdx.y * JSPAN;
    int lane = tid & 31;
    int w = tid >> 5;
    int wi = w >> 1;
    int wd = w & 1;

    int er0 = tid >> 3, ec0 = (tid & 7) * 4;
    int er1 = (tid + 256) >> 3, ec1 = ec0;
    const uint4* pe0 = (const uint4*)(g_e2 + (size_t)(i0 + er0) * N + jbeg + ec0);
    const uint4* pe1 = (const uint4*)(g_e2 + (size_t)(i0 + er1) * N + jbeg + ec1);

    wmma::fragment<wmma::accumulator, 16, 16, 16, float> acc[4];
#pragma unroll
    for (int dt = 0; dt < 4; dt++) wmma::fill_fragment(acc[dt], 0.f);

    uint4 ue0, ue1, ux[4];
    ue0 = pe0[0];
    ue1 = pe1[0];
#pragma unroll
    for (int m = 0; m < 4; m++) {
        int k = tid + 256 * m;
        int jr = k >> 5, c4 = (k & 31) * 4;
        ux[m] = *(const uint4*)(g_x2 + (jbeg + jr) * D + c4);
    }

    for (int jc = 0; jc < JSPAN; jc += 32) {
        {
            *(uint2*)&sEhi[er0][ec0] = make_uint2(
                (ue0.x & 0xffffu) | (ue0.y << 16), (ue0.z & 0xffffu) | (ue0.w << 16));
            *(uint2*)&sElo[er0][ec0] = make_uint2(
                (ue0.x >> 16) | (ue0.y & 0xffff0000u), (ue0.z >> 16) | (ue0.w & 0xffff0000u));
            *(uint2*)&sEhi[er1][ec1] = make_uint2(
                (ue1.x & 0xffffu) | (ue1.y << 16), (ue1.z & 0xffffu) | (ue1.w << 16));
            *(uint2*)&sElo[er1][ec1] = make_uint2(
                (ue1.x >> 16) | (ue1.y & 0xffff0000u), (ue1.z >> 16) | (ue1.w & 0xffff0000u));
#pragma unroll
            for (int m = 0; m < 4; m++) {
                int k = tid + 256 * m;
                int jr = k >> 5, c4 = (k & 31) * 4;
                *(uint2*)&sXhi[jr][c4] = make_uint2(
                    (ux[m].x & 0xffffu) | (ux[m].y << 16),
                    (ux[m].z & 0xffffu) | (ux[m].w << 16));
                *(uint2*)&sXlo[jr][c4] = make_uint2(
                    (ux[m].x >> 16) | (ux[m].y & 0xffff0000u),
                    (ux[m].z >> 16) | (ux[m].w & 0xffff0000u));
            }
        }
        __syncthreads();

        int jn = jc + 32;
        if (jn < JSPAN) {
            ue0 = pe0[jn / 4];
            ue1 = pe1[jn / 4];
#pragma unroll
            for (int m = 0; m < 4; m++) {
                int k = tid + 256 * m;
                int jr = k >> 5, c4 = (k & 31) * 4;
                ux[m] = *(const uint4*)(g_x2 + (jbeg + jn + jr) * D + c4);
            }
        }

#pragma unroll
        for (int jj = 0; jj < 32; jj += 16) {
            wmma::fragment<wmma::matrix_a, 16, 16, 16, __nv_bfloat16, wmma::row_major> ahi, alo;
            wmma::load_matrix_sync(ahi, &sEhi[wi * 16][jj], 40);
            wmma::load_matrix_sync(alo, &sElo[wi * 16][jj], 40);
#pragma unroll
            for (int dt = 0; dt < 4; dt++) {
                wmma::fragment<wmma::matrix_b, 16, 16, 16, __nv_bfloat16, wmma::row_major> bhi, blo;
                wmma::load_matrix_sync(bhi, &sXhi[jj][wd * 64 + dt * 16], 136);
                wmma::load_matrix_sync(blo, &sXlo[jj][wd * 64 + dt * 16], 136);
                wmma::mma_sync(acc[dt], ahi, bhi, acc[dt]);
                wmma::mma_sync(acc[dt], ahi, blo, acc[dt]);
                wmma::mma_sync(acc[dt], alo, bhi, acc[dt]);
            }
        }
        __syncthreads();
    }

    float* dstw = out + (size_t)(i0 + wi * 16) * D + wd * 64;
#pragma unroll
    for (int dt = 0; dt < 4; dt++) {
        wmma::store_matrix_sync(&sOut[w][0], acc[dt], 16, wmma::mem_row_major);
        __syncwarp();
#pragma unroll
        for (int q = lane; q < 256; q += 32) {
            int rr = q >> 4, cc = q & 15;
            atomicAdd(dstw + (size_t)rr * D + dt * 16 + cc, sOut[w][q]);
        }
        __syncwarp();
    }
}

// ================= launch =================
extern "C" void kernel_launch(void* const* d_in, const int* in_sizes, int n_in,
                              void* d_out, int out_size) {
    const float* inputs   = (const float*)d_in[0];
    const float* relation = (const float*)d_in[1];
    const float* rel_mask = (const float*)d_in[2];
    const float* w_rel    = (const float*)d_in[3];
    const float* b_rel    = (const float*)d_in[4];
    const float* w_head   = (const float*)d_in[5];
    const float* b_head   = (const float*)d_in[6];
    const float* w_tail   = (const float*)d_in[7];
    const float* b_tail   = (const float*)d_in[8];
    float* out = (float*)d_out;

    k_headtail<<<256, 256>>>(inputs, w_head, b_head, w_tail, b_tail, out);   // idx 0
    k_logexp<<<(N * N) / (TP * NT), 256>>>(relation, rel_mask, w_rel, b_rel); // idx 1
    k_xsplit<<<256, 256>>>(inputs);                                          // idx 2
    k_gemm<<<dim3(N / ITILE, KSPLIT), 256>>>(out);                           // idx 3 (profiled)
}